// round 5
// baseline (speedup 1.0000x reference)
#include <cuda_runtime.h>
#include <math.h>
#include <stdint.h>

#define BB 4
#define NN 100000
#define KK 16
#define NPAIR (NN / 2)
#define EPSF 1e-6f
#define W_CE 2.0f
#define W_DICE 0.1f

#define GX 111                 // blocks per batch (444 total = 3/SM)
#define NBLK (GX * BB)
#define NWPB 8                 // warps per block
#define TP 64                  // pairs per tile (128 rows)
#define NTILES ((NPAIR + TP - 1) / TP)   // 782 (tail tile = 16 pairs)
#define ENT 544                // padded slot; real: 256 D | 256 INTER | 16 S1M
#define NE_REAL 528
#define NE_TOT (BB * NE_REAL)  // 2112

struct Part { float e[ENT]; };
__device__ Part g_part[NBLK];
__device__ int g_count;        // self-resetting

// ---------------------------------------------------------------------------
struct Stg {
    float m[2][TP * 32];   // mask tiles (2048 floats each)
    float g[2][TP * 32];   // gt tiles
    float v[2][TP * 2];    // valid tiles
};
struct Epi {
    float pti[NWPB][ENT];
    float facc[NE_TOT];
};
union ShU { Stg stg; Epi epi; };   // 33KB stage phase / 26KB epilogue phase

// ---------------------------------------------------------------------------
__device__ __forceinline__ unsigned long long pack_dup(float x) {
    unsigned long long r;
    unsigned int u = __float_as_uint(x);
    asm("mov.b64 %0, {%1, %1};" : "=l"(r) : "r"(u));
    return r;
}
__device__ __forceinline__ void fma2(unsigned long long& acc,
                                     unsigned long long a,
                                     unsigned long long b) {
    asm("fma.rn.f32x2 %0, %1, %2, %0;" : "+l"(acc) : "l"(a), "l"(b));
}
__device__ __forceinline__ float lo32(unsigned long long x) {
    return __uint_as_float((unsigned int)(x & 0xffffffffULL));
}
__device__ __forceinline__ float hi32(unsigned long long x) {
    return __uint_as_float((unsigned int)(x >> 32));
}
__device__ __forceinline__ void cpa16(uint32_t saddr, const void* gptr) {
    asm volatile("cp.async.cg.shared.global [%0], [%1], 16;"
                 :: "r"(saddr), "l"(gptr));
}

// ---------------------------------------------------------------------------
__global__ void __launch_bounds__(256, 3) fused_kernel(
    const float* __restrict__ mask,
    const float* __restrict__ gt,
    const float* __restrict__ valid,
    float* __restrict__ out) {
    __shared__ ShU sh;
    __shared__ float v1m[NWPB][32];
    __shared__ float cost[BB][KK][KK];
    __shared__ float mS1M[BB][KK], mSUMM[BB][KK], mSUMG[BB][KK], mV[BB];
    __shared__ int colmap[BB][KK];
    __shared__ float rce[BB * KK], rdice[BB * KK];
    __shared__ int is_last;

    const int b = blockIdx.y;
    const int bx = blockIdx.x;
    const int t = threadIdx.x;
    const int lane = t & 31;
    const int w = t >> 5;
    const int i = lane & 15;   // cost-row index owned by this lane
    const int jh = lane >> 4;  // j-half (j = jh*8 .. jh*8+7); also row-of-pair
    const unsigned FULL = 0xffffffffu;

    const float* mask_b = mask + (size_t)b * NN * KK;
    const float* gt_b = gt + (size_t)b * NN * KK;
    const float* val_b = valid + (size_t)b * NN;

    const uint32_t sm_m0 = (uint32_t)__cvta_generic_to_shared(&sh.stg.m[0][0]);
    const uint32_t sm_g0 = (uint32_t)__cvta_generic_to_shared(&sh.stg.g[0][0]);
    const uint32_t sm_v0 = (uint32_t)__cvta_generic_to_shared(&sh.stg.v[0][0]);

    // 8 u64 accumulators: aX[k] covers j = jh*8 + {2k, 2k+1}
    unsigned long long aD[4], aI[4];
#pragma unroll
    for (int k = 0; k < 4; k++) { aD[k] = 0ull; aI[k] = 0ull; }
    float s1m = 0.0f;

    // ---- stage fill helper (inlined via lambda-ish macro style) ----
    auto fill_stage = [&](int tile, int s) {
        const int tb = tile * TP;
        const int np = min(TP, NPAIR - tb);
        const int rows = 2 * np;
        const int nchunk = rows * 4;            // 16B chunks (mask & gt)
        const float* gm = mask_b + (size_t)tb * 32;
        const float* gg = gt_b + (size_t)tb * 32;
        const float* gv = val_b + (size_t)tb * 2;
        const uint32_t dm = sm_m0 + (uint32_t)s * (TP * 32 * 4);
        const uint32_t dg = sm_g0 + (uint32_t)s * (TP * 32 * 4);
        const uint32_t dv = sm_v0 + (uint32_t)s * (TP * 2 * 4);
        if (t < nchunk) {
            cpa16(dm + t * 16, gm + t * 4);
            cpa16(dg + t * 16, gg + t * 4);
        }
        if (t + 256 < nchunk) {
            cpa16(dm + (t + 256) * 16, gm + (t + 256) * 4);
            cpa16(dg + (t + 256) * 16, gg + (t + 256) * 4);
        }
        if (t < rows / 4) cpa16(dv + t * 16, gv + t * 4);
    };

    // ---- pipelined main loop ----
    int s = 0;
    fill_stage(bx, 0);
    asm volatile("cp.async.commit_group;" ::: "memory");

    for (int ti = bx; ti < NTILES; ti += GX) {
        const int tn = ti + GX;
        if (tn < NTILES) {
            fill_stage(tn, s ^ 1);
            asm volatile("cp.async.commit_group;" ::: "memory");
            asm volatile("cp.async.wait_group 1;" ::: "memory");
        } else {
            asm volatile("cp.async.wait_group 0;" ::: "memory");
        }
        __syncthreads();

        const int np = min(TP, NPAIR - ti * TP);
        const float* smS = sh.stg.m[s];
        const float* sgS = sh.stg.g[s];
        const float* svS = sh.stg.v[s];

        for (int p = w; p < np; p += NWPB) {
            const float* smg = sgS + p * 32;
            float m = smS[p * 32 + jh * 16 + i];
            float2 v2 = *(const float2*)(svS + p * 2);
            float vown = jh ? v2.y : v2.x;

            ulonglong2 o0 = *(const ulonglong2*)(smg + jh * 24);
            ulonglong2 o1 = *(const ulonglong2*)(smg + jh * 24 + 4);
            ulonglong2 x0 = *(const ulonglong2*)(smg + 16 - 8 * jh);
            ulonglong2 x1 = *(const ulonglong2*)(smg + 20 - 8 * jh);

            float mc = fminf(fmaxf(m, EPSF), 1.0f - EPSF);
            float l1 = __log2f(mc);
            float l2 = __log2f(1.0f - mc);
            float down = vown * (l2 - l1);   // D weight (log2 space)
            float rown = vown * m;           // INTER weight
            s1m -= vown * l2;                // S1M (log2 space)

            float doth = __shfl_xor_sync(FULL, down, 16);
            float roth = __shfl_xor_sync(FULL, rown, 16);

            unsigned long long Dw = pack_dup(down), Rw = pack_dup(rown);
            unsigned long long Dx = pack_dup(doth), Rx = pack_dup(roth);

            fma2(aD[0], Dw, o0.x); fma2(aD[1], Dw, o0.y);
            fma2(aD[2], Dw, o1.x); fma2(aD[3], Dw, o1.y);
            fma2(aI[0], Rw, o0.x); fma2(aI[1], Rw, o0.y);
            fma2(aI[2], Rw, o1.x); fma2(aI[3], Rw, o1.y);

            fma2(aD[0], Dx, x0.x); fma2(aD[1], Dx, x0.y);
            fma2(aD[2], Dx, x1.x); fma2(aD[3], Dx, x1.y);
            fma2(aI[0], Rx, x0.x); fma2(aI[1], Rx, x0.y);
            fma2(aI[2], Rx, x1.x); fma2(aI[3], Rx, x1.y);
        }
        __syncthreads();
        s ^= 1;
    }

    // ---- per-warp -> shared (epilogue aliases the stage buffers) ----
    v1m[w][lane] = s1m;
    {
        const int basej = i * 16 + jh * 8;
#pragma unroll
        for (int k = 0; k < 4; k++) {
            sh.epi.pti[w][basej + 2 * k] = lo32(aD[k]);
            sh.epi.pti[w][basej + 2 * k + 1] = hi32(aD[k]);
            sh.epi.pti[w][256 + basej + 2 * k] = lo32(aI[k]);
            sh.epi.pti[w][256 + basej + 2 * k + 1] = hi32(aI[k]);
        }
    }
    __syncthreads();

    // ---- block reduce -> deterministic per-block partial slot ----
    Part* gp = &g_part[b * GX + bx];
#pragma unroll
    for (int e0 = 0; e0 < 512; e0 += 256) {
        int e = e0 + t;
        float sum = 0.0f;
#pragma unroll
        for (int ww = 0; ww < NWPB; ww++) sum += sh.epi.pti[ww][e];
        gp->e[e] = sum;
    }
    if (t < 16) {
        float sum = 0.0f;
#pragma unroll
        for (int ww = 0; ww < NWPB; ww++) sum += v1m[ww][t] + v1m[ww][t + 16];
        gp->e[512 + t] = sum;
    }

    __threadfence();
    __syncthreads();
    if (t == 0) {
        int old = atomicAdd(&g_count, 1);
        is_last = (old == NBLK - 1);
    }
    __syncthreads();
    if (!is_last) return;

    if (t == 0) g_count = 0;

    // ---- final reduce: 9 entries per thread, jammed for MLP ----
    {
        float sacc[9];
        const float* bas[9];
        int ok[9];
#pragma unroll
        for (int k = 0; k < 9; k++) {
            int q = t + k * 256;
            ok[k] = (q < NE_TOT);
            sacc[k] = 0.0f;
            if (ok[k]) {
                int bb2 = q / NE_REAL;
                int e = q - bb2 * NE_REAL;
                bas[k] = &g_part[bb2 * GX].e[e];
            } else {
                bas[k] = &g_part[0].e[0];
            }
        }
        for (int gx = 0; gx < GX; gx++) {
#pragma unroll
            for (int k = 0; k < 9; k++)
                if (ok[k]) sacc[k] += bas[k][(size_t)gx * ENT];
        }
#pragma unroll
        for (int k = 0; k < 9; k++) {
            int q = t + k * 256;
            if (ok[k]) sh.epi.facc[q] = sacc[k];
        }
    }
    __syncthreads();

    // ---- marginals from INTER (+ direct S1M) ----
    if (t < BB * KK) {
        int bb2 = t / KK, q = t % KK;
        const float* F = sh.epi.facc + bb2 * NE_REAL;
        float summ = 0.0f, sumg = 0.0f;
#pragma unroll
        for (int x = 0; x < KK; x++) {
            summ += F[256 + q * 16 + x];   // row sum of INTER
            sumg += F[256 + x * 16 + q];   // col sum of INTER
        }
        mS1M[bb2][q] = F[512 + q];
        mSUMM[bb2][q] = summ;
        mSUMG[bb2][q] = sumg;
    }
    __syncthreads();
    if (t < BB) {
        float v = 0.0f;
#pragma unroll
        for (int x = 0; x < KK; x++) v += mSUMG[t][x];
        mV[t] = v;
    }
    __syncthreads();

    // ---- cost matrices ----
    const float LN2 = 0.69314718055994530942f;
    for (int idx = t; idx < BB * 256; idx += 256) {
        int bb2 = idx >> 8;
        int r = idx & 255;
        int ii = r >> 4, jj = r & 15;
        const float* F = sh.epi.facc + bb2 * NE_REAL;
        float denom = fmaxf(mV[bb2], 1.0f);
        float ce = LN2 * (F[ii * 16 + jj] + mS1M[bb2][ii]) / denom;
        float dice = 1.0f - 2.0f * F[256 + ii * 16 + jj] /
                                (mSUMM[bb2][ii] + mSUMG[bb2][jj] + EPSF);
        cost[bb2][ii][jj] = W_CE * ce + W_DICE * dice;
    }
    __syncthreads();

    // ---- warp-parallel Hungarian (JV), one warp per batch ----
    if (w < BB) {
        const int bb2 = w;
        float ur = 0.0f;
        float vv = 0.0f;
        int pcol = 0;

        for (int ii = 1; ii <= KK; ii++) {
            if (lane == 0) pcol = ii;
            float minv = 1e30f;
            int way = 0;
            int used = 0;
            int rowcov = 0;
            int j0 = 0;

            while (true) {
                if (lane == j0) used = 1;
                int i0 = __shfl_sync(FULL, pcol, j0);
                if (lane == i0) rowcov = 1;
                float u_i0 = __shfl_sync(FULL, ur, i0);

                int active = (lane >= 1 && lane <= KK && !used);
                if (active) {
                    float c = cost[bb2][i0 - 1][lane - 1];
                    float cur = c - u_i0 - vv;
                    if (cur < minv) { minv = cur; way = j0; }
                }
                float val = active ? minv : 1e30f;
                float red = val;
#pragma unroll
                for (int off = 16; off; off >>= 1)
                    red = fminf(red, __shfl_xor_sync(FULL, red, off));
                unsigned bal = __ballot_sync(FULL, val == red);
                int j1 = __ffs(bal) - 1;
                float delta = red;

                if (rowcov) ur += delta;
                if (used) vv -= delta;
                else if (lane >= 1 && lane <= KK) minv -= delta;

                j0 = j1;
                int pj = __shfl_sync(FULL, pcol, j0);
                if (pj == 0) break;
            }
            while (j0 != 0) {
                int j1 = __shfl_sync(FULL, way, j0);
                int pv = __shfl_sync(FULL, pcol, j1);
                if (lane == j0) pcol = pv;
                j0 = j1;
            }
        }
        if (lane >= 1 && lane <= KK) colmap[bb2][pcol - 1] = lane - 1;
    }
    __syncthreads();

    // ---- loss ----
    if (t < BB * KK) {
        int bb2 = t / KK, ii = t % KK;
        int jj = colmap[bb2][ii];
        const float* F = sh.epi.facc + bb2 * NE_REAL;
        rce[t] = LN2 * (F[ii * 16 + jj] + mS1M[bb2][ii]);
        rdice[t] = 1.0f - 2.0f * F[256 + ii * 16 + jj] /
                              (mSUMM[bb2][ii] + mSUMG[bb2][jj] + EPSF);
    }
    __syncthreads();

    if (t == 0) {
        float cs = 0.0f, ds = 0.0f, vt = 0.0f;
        for (int x = 0; x < BB * KK; x++) { cs += rce[x]; ds += rdice[x]; }
        for (int bb2 = 0; bb2 < BB; bb2++) vt += mV[bb2];
        float l_ce = cs / (fmaxf(vt, 1.0f) * (float)KK);
        float l_dice = ds / (float)(BB * KK);
        out[0] = W_CE * l_ce + W_DICE * l_dice;
    }
}

// ---------------------------------------------------------------------------
extern "C" void kernel_launch(void* const* d_in, const int* in_sizes, int n_in,
                              void* d_out, int out_size) {
    const float* mask = (const float*)d_in[0];
    const float* gt = (const float*)d_in[1];
    const float* valid = (const float*)d_in[2];
    float* out = (float*)d_out;

    dim3 grid(GX, BB);
    fused_kernel<<<grid, 256>>>(mask, gt, valid, out);
}

// round 6
// speedup vs baseline: 1.0535x; 1.0535x over previous
#include <cuda_runtime.h>
#include <math.h>
#include <stdint.h>

#define BB 4
#define NN 100000
#define KK 16
#define NPAIR (NN / 2)
#define EPSF 1e-6f
#define W_CE 2.0f
#define W_DICE 0.1f

#define GX 111                 // blocks per batch (444 total = 3/SM)
#define NBLK (GX * BB)
#define NWPB 8                 // warps per block
#define TP 64                  // pairs per tile (128 rows)
#define NTILES ((NPAIR + TP - 1) / TP)   // 782 (tail = 16 pairs)
#define ENT 544                // padded slot; real: 256 D | 256 INTER | 16 S1M
#define NE_REAL 528
#define NE_TOT (BB * NE_REAL)  // 2112

struct Part { float e[ENT]; };
__device__ Part g_part[NBLK];
__device__ int g_count;        // self-resetting

// ---------------------------------------------------------------------------
struct __align__(16) Stg {
    float m[2][TP * 32];   // mask tiles (8KB each)
    float g[2][TP * 32];   // gt tiles
    float v[2][TP * 2];    // valid tiles (512B each)
};
struct __align__(16) Epi {
    float pti[NWPB][ENT];
    float facc[NE_TOT];
};
union ShU { Stg stg; Epi epi; };

// ---------------------------------------------------------------------------
__device__ __forceinline__ unsigned long long pack_dup(float x) {
    unsigned long long r;
    unsigned int u = __float_as_uint(x);
    asm("mov.b64 %0, {%1, %1};" : "=l"(r) : "r"(u));
    return r;
}
__device__ __forceinline__ void fma2(unsigned long long& acc,
                                     unsigned long long a,
                                     unsigned long long b) {
    asm("fma.rn.f32x2 %0, %1, %2, %0;" : "+l"(acc) : "l"(a), "l"(b));
}
__device__ __forceinline__ float lo32(unsigned long long x) {
    return __uint_as_float((unsigned int)(x & 0xffffffffULL));
}
__device__ __forceinline__ float hi32(unsigned long long x) {
    return __uint_as_float((unsigned int)(x >> 32));
}
__device__ __forceinline__ void mbar_init(uint32_t mbar, uint32_t cnt) {
    asm volatile("mbarrier.init.shared.b64 [%0], %1;" :: "r"(mbar), "r"(cnt)
                 : "memory");
}
__device__ __forceinline__ void mbar_expect_tx(uint32_t mbar, uint32_t bytes) {
    asm volatile("mbarrier.arrive.expect_tx.shared.b64 _, [%0], %1;"
                 :: "r"(mbar), "r"(bytes) : "memory");
}
__device__ __forceinline__ void bulk_g2s(uint32_t dst, const void* src,
                                         uint32_t bytes, uint32_t mbar) {
    asm volatile(
        "cp.async.bulk.shared::cta.global.mbarrier::complete_tx::bytes "
        "[%0], [%1], %2, [%3];"
        :: "r"(dst), "l"(src), "r"(bytes), "r"(mbar) : "memory");
}
__device__ __forceinline__ void mbar_wait(uint32_t mbar, uint32_t phase) {
    uint32_t done;
    asm volatile(
        "{\n\t.reg .pred p;\n\t"
        "mbarrier.try_wait.parity.acquire.cta.shared::cta.b64 p, [%1], %2;\n\t"
        "selp.b32 %0, 1, 0, p;\n\t}"
        : "=r"(done) : "r"(mbar), "r"(phase) : "memory");
    if (!done) {
        asm volatile(
            "{\n\t.reg .pred P1;\n\t"
            "WL_%=:\n\t"
            "mbarrier.try_wait.parity.acquire.cta.shared::cta.b64 P1, [%0], %1, 0x989680;\n\t"
            "@P1 bra.uni WD_%=;\n\t"
            "bra.uni WL_%=;\n\t"
            "WD_%=:\n\t}"
            :: "r"(mbar), "r"(phase) : "memory");
    }
}

// ---------------------------------------------------------------------------
__global__ void __launch_bounds__(256, 3) fused_kernel(
    const float* __restrict__ mask,
    const float* __restrict__ gt,
    const float* __restrict__ valid,
    float* __restrict__ out) {
    __shared__ ShU sh;
    __shared__ __align__(8) unsigned long long mbar_full[2];
    __shared__ float v1m[NWPB][32];
    __shared__ float cost[BB][KK][KK];
    __shared__ float mS1M[BB][KK], mSUMM[BB][KK], mSUMG[BB][KK], mV[BB];
    __shared__ int colmap[BB][KK];
    __shared__ float rce[BB * KK], rdice[BB * KK];
    __shared__ int is_last;

    const int b = blockIdx.y;
    const int bx = blockIdx.x;
    const int t = threadIdx.x;
    const int lane = t & 31;
    const int w = t >> 5;
    const int i = lane & 15;   // cost-row index owned by this lane
    const int jh = lane >> 4;  // j-half; also row-of-pair for d/r
    const unsigned FULL = 0xffffffffu;

    const float* mask_b = mask + (size_t)b * NN * KK;
    const float* gt_b = gt + (size_t)b * NN * KK;
    const float* val_b = valid + (size_t)b * NN;

    const uint32_t sm_m0 = (uint32_t)__cvta_generic_to_shared(&sh.stg.m[0][0]);
    const uint32_t sm_g0 = (uint32_t)__cvta_generic_to_shared(&sh.stg.g[0][0]);
    const uint32_t sm_v0 = (uint32_t)__cvta_generic_to_shared(&sh.stg.v[0][0]);
    const uint32_t mb0 = (uint32_t)__cvta_generic_to_shared(&mbar_full[0]);

    const int nt = (NTILES - bx + GX - 1) / GX;   // rounds for this block

    // issue one tile into buffer s (single thread)
    auto issue = [&](int rr, int s) {
        const int ti = bx + rr * GX;
        const int tb = ti * TP;
        const int np = min(TP, NPAIR - tb);
        const uint32_t mB = (uint32_t)(np * 128);   // 2np rows * 64B
        const uint32_t vB = (uint32_t)(np * 8);
        const uint32_t bar = mb0 + (uint32_t)s * 8;
        mbar_expect_tx(bar, mB * 2 + vB);
        bulk_g2s(sm_m0 + (uint32_t)s * (TP * 128), mask_b + (size_t)tb * 32, mB, bar);
        bulk_g2s(sm_g0 + (uint32_t)s * (TP * 128), gt_b + (size_t)tb * 32, mB, bar);
        bulk_g2s(sm_v0 + (uint32_t)s * (TP * 8), val_b + (size_t)tb * 2, vB, bar);
    };

    if (t == 0) { mbar_init(mb0, 1); mbar_init(mb0 + 8, 1); }
    __syncthreads();
    if (t == 0) {
        issue(0, 0);
        if (nt > 1) issue(1, 1);
    }

    // 8 u64 accumulators: aX[k] covers j = jh*8 + {2k, 2k+1}
    unsigned long long aD[4], aI[4];
#pragma unroll
    for (int k = 0; k < 4; k++) { aD[k] = 0ull; aI[k] = 0ull; }
    float s1m = 0.0f;

    for (int r = 0; r < nt; r++) {
        const int s = r & 1;
        const uint32_t ph = (uint32_t)((r >> 1) & 1);
        mbar_wait(mb0 + (uint32_t)s * 8, ph);

        const int np = min(TP, NPAIR - (bx + r * GX) * TP);
        const float* smS = sh.stg.m[s];
        const float* sgS = sh.stg.g[s];
        const float* svS = sh.stg.v[s];

#pragma unroll 2
        for (int p = w; p < np; p += NWPB) {
            const float* smg = sgS + p * 32;
            float m = smS[p * 32 + jh * 16 + i];
            float2 v2 = *(const float2*)(svS + p * 2);
            float vown = jh ? v2.y : v2.x;

            ulonglong2 o0 = *(const ulonglong2*)(smg + jh * 24);
            ulonglong2 o1 = *(const ulonglong2*)(smg + jh * 24 + 4);
            ulonglong2 x0 = *(const ulonglong2*)(smg + 16 - 8 * jh);
            ulonglong2 x1 = *(const ulonglong2*)(smg + 20 - 8 * jh);

            float mc = fminf(fmaxf(m, EPSF), 1.0f - EPSF);
            float l1 = __log2f(mc);
            float l2 = __log2f(1.0f - mc);
            float down = vown * (l2 - l1);   // D weight (log2 space)
            float rown = vown * m;           // INTER weight
            s1m -= vown * l2;                // S1M (log2 space)

            float doth = __shfl_xor_sync(FULL, down, 16);
            float roth = __shfl_xor_sync(FULL, rown, 16);

            unsigned long long Dw = pack_dup(down), Rw = pack_dup(rown);
            unsigned long long Dx = pack_dup(doth), Rx = pack_dup(roth);

            fma2(aD[0], Dw, o0.x); fma2(aD[1], Dw, o0.y);
            fma2(aD[2], Dw, o1.x); fma2(aD[3], Dw, o1.y);
            fma2(aI[0], Rw, o0.x); fma2(aI[1], Rw, o0.y);
            fma2(aI[2], Rw, o1.x); fma2(aI[3], Rw, o1.y);

            fma2(aD[0], Dx, x0.x); fma2(aD[1], Dx, x0.y);
            fma2(aD[2], Dx, x1.x); fma2(aD[3], Dx, x1.y);
            fma2(aI[0], Rx, x0.x); fma2(aI[1], Rx, x0.y);
            fma2(aI[2], Rx, x1.x); fma2(aI[3], Rx, x1.y);
        }
        __syncthreads();              // all reads of buffer s done
        if (t == 0 && r + 2 < nt) issue(r + 2, s);
    }

    // ---- per-warp -> shared (epilogue aliases the stage buffers) ----
    v1m[w][lane] = s1m;
    {
        const int basej = i * 16 + jh * 8;
#pragma unroll
        for (int k = 0; k < 4; k++) {
            sh.epi.pti[w][basej + 2 * k] = lo32(aD[k]);
            sh.epi.pti[w][basej + 2 * k + 1] = hi32(aD[k]);
            sh.epi.pti[w][256 + basej + 2 * k] = lo32(aI[k]);
            sh.epi.pti[w][256 + basej + 2 * k + 1] = hi32(aI[k]);
        }
    }
    __syncthreads();

    // ---- block reduce -> deterministic per-block partial slot ----
    Part* gp = &g_part[b * GX + bx];
#pragma unroll
    for (int e0 = 0; e0 < 512; e0 += 256) {
        int e = e0 + t;
        float sum = 0.0f;
#pragma unroll
        for (int ww = 0; ww < NWPB; ww++) sum += sh.epi.pti[ww][e];
        gp->e[e] = sum;
    }
    if (t < 16) {
        float sum = 0.0f;
#pragma unroll
        for (int ww = 0; ww < NWPB; ww++) sum += v1m[ww][t] + v1m[ww][t + 16];
        gp->e[512 + t] = sum;
    }

    __threadfence();
    __syncthreads();
    if (t == 0) {
        int old = atomicAdd(&g_count, 1);
        is_last = (old == NBLK - 1);
    }
    __syncthreads();
    if (!is_last) return;

    if (t == 0) g_count = 0;

    // ---- final reduce: 9 entries per thread, jammed for MLP ----
    {
        float sacc[9];
        const float* bas[9];
        int ok[9];
#pragma unroll
        for (int k = 0; k < 9; k++) {
            int q = t + k * 256;
            ok[k] = (q < NE_TOT);
            sacc[k] = 0.0f;
            if (ok[k]) {
                int bb2 = q / NE_REAL;
                int e = q - bb2 * NE_REAL;
                bas[k] = &g_part[bb2 * GX].e[e];
            } else {
                bas[k] = &g_part[0].e[0];
            }
        }
        for (int gx = 0; gx < GX; gx++) {
#pragma unroll
            for (int k = 0; k < 9; k++)
                if (ok[k]) sacc[k] += bas[k][(size_t)gx * ENT];
        }
#pragma unroll
        for (int k = 0; k < 9; k++) {
            int q = t + k * 256;
            if (ok[k]) sh.epi.facc[q] = sacc[k];
        }
    }
    __syncthreads();

    // ---- marginals from INTER (+ direct S1M) ----
    if (t < BB * KK) {
        int bb2 = t / KK, q = t % KK;
        const float* F = sh.epi.facc + bb2 * NE_REAL;
        float summ = 0.0f, sumg = 0.0f;
#pragma unroll
        for (int x = 0; x < KK; x++) {
            summ += F[256 + q * 16 + x];   // row sum of INTER
            sumg += F[256 + x * 16 + q];   // col sum of INTER
        }
        mS1M[bb2][q] = F[512 + q];
        mSUMM[bb2][q] = summ;
        mSUMG[bb2][q] = sumg;
    }
    __syncthreads();
    if (t < BB) {
        float v = 0.0f;
#pragma unroll
        for (int x = 0; x < KK; x++) v += mSUMG[t][x];
        mV[t] = v;
    }
    __syncthreads();

    // ---- cost matrices ----
    const float LN2 = 0.69314718055994530942f;
    for (int idx = t; idx < BB * 256; idx += 256) {
        int bb2 = idx >> 8;
        int r = idx & 255;
        int ii = r >> 4, jj = r & 15;
        const float* F = sh.epi.facc + bb2 * NE_REAL;
        float denom = fmaxf(mV[bb2], 1.0f);
        float ce = LN2 * (F[ii * 16 + jj] + mS1M[bb2][ii]) / denom;
        float dice = 1.0f - 2.0f * F[256 + ii * 16 + jj] /
                                (mSUMM[bb2][ii] + mSUMG[bb2][jj] + EPSF);
        cost[bb2][ii][jj] = W_CE * ce + W_DICE * dice;
    }
    __syncthreads();

    // ---- warp-parallel Hungarian (JV), one warp per batch ----
    if (w < BB) {
        const int bb2 = w;
        float ur = 0.0f;
        float vv = 0.0f;
        int pcol = 0;

        for (int ii = 1; ii <= KK; ii++) {
            if (lane == 0) pcol = ii;
            float minv = 1e30f;
            int way = 0;
            int used = 0;
            int rowcov = 0;
            int j0 = 0;

            while (true) {
                if (lane == j0) used = 1;
                int i0 = __shfl_sync(FULL, pcol, j0);
                if (lane == i0) rowcov = 1;
                float u_i0 = __shfl_sync(FULL, ur, i0);

                int active = (lane >= 1 && lane <= KK && !used);
                if (active) {
                    float c = cost[bb2][i0 - 1][lane - 1];
                    float cur = c - u_i0 - vv;
                    if (cur < minv) { minv = cur; way = j0; }
                }
                float val = active ? minv : 1e30f;
                float red = val;
#pragma unroll
                for (int off = 16; off; off >>= 1)
                    red = fminf(red, __shfl_xor_sync(FULL, red, off));
                unsigned bal = __ballot_sync(FULL, val == red);
                int j1 = __ffs(bal) - 1;
                float delta = red;

                if (rowcov) ur += delta;
                if (used) vv -= delta;
                else if (lane >= 1 && lane <= KK) minv -= delta;

                j0 = j1;
                int pj = __shfl_sync(FULL, pcol, j0);
                if (pj == 0) break;
            }
            while (j0 != 0) {
                int j1 = __shfl_sync(FULL, way, j0);
                int pv = __shfl_sync(FULL, pcol, j1);
                if (lane == j0) pcol = pv;
                j0 = j1;
            }
        }
        if (lane >= 1 && lane <= KK) colmap[bb2][pcol - 1] = lane - 1;
    }
    __syncthreads();

    // ---- loss ----
    if (t < BB * KK) {
        int bb2 = t / KK, ii = t % KK;
        int jj = colmap[bb2][ii];
        const float* F = sh.epi.facc + bb2 * NE_REAL;
        rce[t] = LN2 * (F[ii * 16 + jj] + mS1M[bb2][ii]);
        rdice[t] = 1.0f - 2.0f * F[256 + ii * 16 + jj] /
                              (mSUMM[bb2][ii] + mSUMG[bb2][jj] + EPSF);
    }
    __syncthreads();

    if (t == 0) {
        float cs = 0.0f, ds = 0.0f, vt = 0.0f;
        for (int x = 0; x < BB * KK; x++) { cs += rce[x]; ds += rdice[x]; }
        for (int bb2 = 0; bb2 < BB; bb2++) vt += mV[bb2];
        float l_ce = cs / (fmaxf(vt, 1.0f) * (float)KK);
        float l_dice = ds / (float)(BB * KK);
        out[0] = W_CE * l_ce + W_DICE * l_dice;
    }
}

// ---------------------------------------------------------------------------
extern "C" void kernel_launch(void* const* d_in, const int* in_sizes, int n_in,
                              void* d_out, int out_size) {
    const float* mask = (const float*)d_in[0];
    const float* gt = (const float*)d_in[1];
    const float* valid = (const float*)d_in[2];
    float* out = (float*)d_out;

    dim3 grid(GX, BB);
    fused_kernel<<<grid, 256>>>(mask, gt, valid, out);
}